// round 14
// baseline (speedup 1.0000x reference)
#include <cuda_runtime.h>
#include <cuda_bf16.h>
#include <math.h>

#define BATCH 4
#define SEQ   2048
#define HDIM  128
#define HEADS 4
#define HD    32
#define RNK   8
#define FEAT  48            // 32 (qk) + 8 (u/v bias) + 8 zero pad
#define KPAD  48
#define VPAD  80
#define APAD  80            // 40 words == 8 mod 32 -> conflict-free LDS.64
#define QTILE 128
#define CHUNK 64
#define KSPLIT 2
#define NCHS  (SEQ / KSPLIT / CHUNK)           // 16 chunks per split
#define NTOT  (BATCH * SEQ * HDIM)
#define LOG2E 1.4426950408889634f
#define ONESBF 0x3F803F80u                     // bf16 {1.0, 1.0}

// attn smem stage layout (bytes)
#define K_OFF    0
#define K_BYTES  (CHUNK * KPAD * 2)            // 6144
#define V_OFF    K_BYTES
#define V_BYTES  (HD * VPAD * 2)               // 5120
#define A_OFF    (V_OFF + V_BYTES)             // 11264
#define A_BYTES  (QTILE * APAD * 2)            // 20480
#define STAGE_SZ (A_OFF + A_BYTES)             // 31744
#define ATTN_SMEM (2 * STAGE_SZ)               // 63488

// fused qkv smem layout (bytes)
#define QF_WQH   0                             // 24*384*4 = 36864 (reused as sq/sk)
#define QF_TSM   36864                         // 32*28*4  = 3584
#define QF_XS    40448                         // 32*132*4 = 16896
#define QF_WS    57344                         // 128*24*4 = 12288
#define QKV_SMEM 69632

// ---------------- static device scratch ------------------------------------
__device__ __align__(16) __nv_bfloat16 g_qa[BATCH * HEADS * SEQ * FEAT];
__device__ __align__(16) __nv_bfloat16 g_ka[BATCH * HEADS * SEQ * FEAT];
__device__ __align__(16) __nv_bfloat16 g_vt[BATCH * HEADS * HD * SEQ];
__device__ __align__(16) __nv_bfloat16 g_adjb[SEQ * SEQ];   // softplus*log2e scaled, key-perm16
__device__ __align__(16) __nv_bfloat16 g_pob[KSPLIT * BATCH * HEADS * SEQ * HD];  // bf16 partials
__device__ __align__(16) float g_pl[KSPLIT * BATCH * HEADS * SEQ];

// ---------------- helpers ---------------------------------------------------
__device__ __forceinline__ unsigned packbf(float lo, float hi) {
    unsigned r;
    asm("cvt.rn.bf16x2.f32 %0, %1, %2;" : "=r"(r) : "f"(hi), "f"(lo));
    return r;
}
__device__ __forceinline__ float bflo(unsigned u) { return __int_as_float(u << 16); }
__device__ __forceinline__ float bfhi(unsigned u) { return __int_as_float(u & 0xffff0000u); }
__device__ __forceinline__ unsigned ex2_bf16x2(unsigned a) {
    unsigned r;
    asm("ex2.approx.ftz.bf16x2 %0, %1;" : "=r"(r) : "r"(a));
    return r;
}

__device__ __host__ __forceinline__ int perm16(int c) {
    int g = c & ~15, c16 = c & 15;
    return g + 4 * ((c16 >> 1) & 3) + 2 * (c16 >> 3) + (c16 & 1);
}

__device__ __forceinline__ void mma16816(float& c0, float& c1, float& c2, float& c3,
                                         unsigned a0, unsigned a1, unsigned a2, unsigned a3,
                                         unsigned b0, unsigned b1) {
    asm volatile("mma.sync.aligned.m16n8k16.row.col.f32.bf16.bf16.f32 "
                 "{%0,%1,%2,%3}, {%4,%5,%6,%7}, {%8,%9}, {%0,%1,%2,%3};"
                 : "+f"(c0), "+f"(c1), "+f"(c2), "+f"(c3)
                 : "r"(a0), "r"(a1), "r"(a2), "r"(a3), "r"(b0), "r"(b1));
}

__device__ __forceinline__ void cp16(unsigned smem_dst, const void* gsrc) {
    asm volatile("cp.async.cg.shared.global [%0], [%1], 16;" :: "r"(smem_dst), "l"(gsrc));
}

// =============================================================================
// Prologue (fused): blocks [0,1024) convert adj fp32 -> bf16 (scaled,
// key-perm16); blocks [1024,1056) write u/v into Q/K aug cols.
// =============================================================================
__global__ __launch_bounds__(256) void prep_kernel(
    const float* __restrict__ adj, const float* __restrict__ adj_scale,
    const float* __restrict__ u, const float* __restrict__ v)
{
    if (blockIdx.x < 1024) {
        const float cs = log1pf(expf(adj_scale[0])) * LOG2E;
        size_t i = (size_t)blockIdx.x * 256 + threadIdx.x;   // 16-el group index
        const float4* src = (const float4*)adj + i * 4;
        float4 fa = src[0], fb = src[1], fc = src[2], fd = src[3];
        float f[16] = {fa.x, fa.y, fa.z, fa.w, fb.x, fb.y, fb.z, fb.w,
                       fc.x, fc.y, fc.z, fc.w, fd.x, fd.y, fd.z, fd.w};
        #pragma unroll
        for (int k = 0; k < 16; k++) f[k] *= cs;
        uint4 wa, wb;
        wa.x = packbf(f[0],  f[1]);  wa.y = packbf(f[8],  f[9]);
        wa.z = packbf(f[2],  f[3]);  wa.w = packbf(f[10], f[11]);
        wb.x = packbf(f[4],  f[5]);  wb.y = packbf(f[12], f[13]);
        wb.z = packbf(f[6],  f[7]);  wb.w = packbf(f[14], f[15]);
        ((uint4*)g_adjb)[i * 2 + 0] = wa;
        ((uint4*)g_adjb)[i * 2 + 1] = wb;
        return;
    }
    int idx = (blockIdx.x - 1024) * 256 + threadIdx.x;
    if (idx >= HEADS * SEQ) return;
    int h = idx >> 11, n = idx & (SEQ - 1);
    unsigned uw[4], vw[4];
    #pragma unroll
    for (int i = 0; i < 4; i++) {
        uw[i] = packbf(u[((size_t)h * SEQ + n) * RNK + 2 * i] * LOG2E,
                       u[((size_t)h * SEQ + n) * RNK + 2 * i + 1] * LOG2E);
        vw[i] = packbf(v[((size_t)h * RNK + 2 * i) * SEQ + n],
                       v[((size_t)h * RNK + 2 * i + 1) * SEQ + n]);
    }
    #pragma unroll
    for (int b = 0; b < BATCH; b++) {
        size_t base = ((size_t)(b * HEADS + h) * SEQ + n) * FEAT + 32;
        #pragma unroll
        for (int i = 0; i < 4; i++) {
            *(unsigned*)&g_qa[base + 4 * i]     = uw[i];
            *(unsigned*)&g_ka[base + 4 * i]     = vw[i];
            *(unsigned*)&g_qa[base + 4 * i + 2] = 0u;
            *(unsigned*)&g_ka[base + 4 * i + 2] = 0u;
        }
    }
}

// =============================================================================
// Kernel A (fused): QKV = (x@Wql+bql)@Wqh+bqh -> bf16 permuted Q/K + V^T.
// 32 rows/block, 384 threads, dynamic smem. Phase 1: T into smem (no global
// round-trip). Phase 2: thread-per-column with Wqh staged, smem transpose
// for coalesced Q/K stores.
// =============================================================================
#define QROWS 32
#define TSPAD 28
#define SQPAD 40
__global__ __launch_bounds__(384) void qkv_fused(
    const float* __restrict__ x, const float* __restrict__ Wql,
    const float* __restrict__ bql, const float* __restrict__ Wqh,
    const float* __restrict__ bqh)
{
    extern __shared__ __align__(16) char dsm[];
    float* wqh = (float*)(dsm + QF_WQH);
    float* tsm = (float*)(dsm + QF_TSM);
    float* xs  = (float*)(dsm + QF_XS);
    float* ws  = (float*)(dsm + QF_WS);

    const int tid  = threadIdx.x;
    const int row0 = blockIdx.x * QROWS;

    // stage x rows (32x128, padded), Wql (128x24), Wqh (24x384)
    for (int e = tid; e < 1024; e += 384) {
        int r = e >> 5, c4 = e & 31;
        *(float4*)&xs[r * 132 + c4 * 4] =
            ((const float4*)(x + (size_t)row0 * HDIM))[e];
    }
    for (int e = tid; e < 768; e += 384)
        ((float4*)ws)[e] = ((const float4*)Wql)[e];
    for (int e = tid; e < 2304; e += 384)
        ((float4*)wqh)[e] = ((const float4*)Wqh)[e];
    __syncthreads();

    // phase 1: threads 0..127 compute T = x@Wql + bql into tsm
    if (tid < 128) {
        const int r    = tid >> 2;
        const int cgrp = (tid & 3) * 6;
        float acc[6];
        #pragma unroll
        for (int j = 0; j < 6; j++) acc[j] = bql[cgrp + j];
        #pragma unroll 4
        for (int d = 0; d < HDIM; d++) {
            float xv = xs[r * 132 + d];
            float2 w01 = *(const float2*)&ws[d * 24 + cgrp];
            float2 w23 = *(const float2*)&ws[d * 24 + cgrp + 2];
            float2 w45 = *(const float2*)&ws[d * 24 + cgrp + 4];
            acc[0] = fmaf(xv, w01.x, acc[0]);
            acc[1] = fmaf(xv, w01.y, acc[1]);
            acc[2] = fmaf(xv, w23.x, acc[2]);
            acc[3] = fmaf(xv, w23.y, acc[3]);
            acc[4] = fmaf(xv, w45.x, acc[4]);
            acc[5] = fmaf(xv, w45.y, acc[5]);
        }
        #pragma unroll
        for (int j = 0; j < 6; j++) tsm[r * TSPAD + cgrp + j] = acc[j];
    }
    __syncthreads();

    // phase 2: one output column per thread
    const int c = tid;
    float wv[24];
    #pragma unroll
    for (int rk = 0; rk < 24; rk++) wv[rk] = wqh[rk * 384 + c];
    const float bias = bqh[c];
    __syncthreads();   // wv in regs; wqh region reusable as sq/sk

    float acc[QROWS];
    #pragma unroll
    for (int row = 0; row < QROWS; row++) {
        float a = bias;
        #pragma unroll
        for (int k4 = 0; k4 < 6; k4++) {
            float4 t = *(const float4*)&tsm[row * TSPAD + k4 * 4];
            a = fmaf(t.x, wv[k4 * 4 + 0], a);
            a = fmaf(t.y, wv[k4 * 4 + 1], a);
            a = fmaf(t.z, wv[k4 * 4 + 2], a);
            a = fmaf(t.w, wv[k4 * 4 + 3], a);
        }
        acc[row] = a;
    }

    const int b  = row0 >> 11;
    const int n0 = row0 & (SEQ - 1);
    const int which = c >> 7;
    const int cc = c & 127;
    const int hh = cc >> 5, dd = cc & 31;
    const float qscale = 0.17677669529663687f * LOG2E;

    __nv_bfloat16* sq = (__nv_bfloat16*)(dsm + QF_WQH);
    __nv_bfloat16* sk = sq + 128 * SQPAD;

    if (which < 2) {
        const int col = perm16(dd);
        __nv_bfloat16* s = (which == 0) ? sq : sk;
        const float sc = (which == 0) ? qscale : 1.0f;
        #pragma unroll
        for (int row = 0; row < QROWS; row++)
            s[(hh * 32 + row) * SQPAD + col] = __float2bfloat16(acc[row] * sc);
    } else {
        size_t base = ((size_t)(b * HEADS + hh) * HD + dd) * SEQ + n0;
        #pragma unroll
        for (int gset = 0; gset < 2; gset++) {
            const float* a = acc + gset * 16;
            uint4 w0, w1;
            w0.x = packbf(a[0],  a[1]);  w0.y = packbf(a[8],  a[9]);
            w0.z = packbf(a[2],  a[3]);  w0.w = packbf(a[10], a[11]);
            w1.x = packbf(a[4],  a[5]);  w1.y = packbf(a[12], a[13]);
            w1.z = packbf(a[6],  a[7]);  w1.w = packbf(a[14], a[15]);
            *(uint4*)&g_vt[base + gset * 16 + 0] = w0;
            *(uint4*)&g_vt[base + gset * 16 + 8] = w1;
        }
    }
    __syncthreads();

    // coalesced Q/K writeout: 2 matrices x 128 out-rows x 4 uint4
    for (int e = tid; e < 1024; e += 384) {
        const int m   = e >> 9;
        const int idx = e & 511;
        const int orow = idx >> 2;
        const int seg  = idx & 3;
        const int ohh = orow >> 5, orr = orow & 31;
        const __nv_bfloat16* s = (m == 0) ? sq : sk;
        uint4 val = *(const uint4*)&s[orow * SQPAD + seg * 8];
        __nv_bfloat16* g = (m == 0) ? g_qa : g_ka;
        *(uint4*)&g[((size_t)(b * HEADS + ohh) * SEQ + n0 + orr) * FEAT + seg * 8] = val;
    }
}

// =============================================================================
// Kernel B: tensor-core attention, split-K. QTILE=128, CHUNK=64, 256 threads.
// adj key-permuted -> LDS.64; rowsum via ones-MMA; paired bf16x2 ex2.
// Partials stored in bf16 (halved store/load traffic).
// =============================================================================
__global__ __launch_bounds__(256, 3) void attn_kernel()
{
    extern __shared__ __align__(16) char smem_raw[];

    const int tid  = threadIdx.x;
    const int lane = tid & 31;
    const int warp = tid >> 5;
    const int gid  = lane >> 2;
    const int tig  = lane & 3;
    const int h = blockIdx.y, b = blockIdx.z;
    const int qt    = blockIdx.x >> 1;
    const int split = blockIdx.x & 1;
    const int q0 = qt * QTILE;
    const int j0base = split * (SEQ / KSPLIT);
    const int qrow = warp * 16;

    const size_t bh     = (size_t)(b * HEADS + h);
    const size_t krow0  = bh * SEQ;
    const size_t vtrow0 = bh * HD;

    const unsigned sbase = (unsigned)__cvta_generic_to_shared(smem_raw);

    unsigned qa[3][4];
    {
        const __nv_bfloat16* q0p = g_qa + (krow0 + q0 + qrow + gid) * FEAT;
        #pragma unroll
        for (int kk = 0; kk < 3; kk++) {
            uint2 t0 = *(const uint2*)(q0p + 16 * kk + 4 * tig);
            uint2 t1 = *(const uint2*)(q0p + 8 * FEAT + 16 * kk + 4 * tig);
            qa[kk][0] = t0.x; qa[kk][1] = t1.x; qa[kk][2] = t0.y; qa[kk][3] = t1.y;
        }
    }

    float o[4][4];
    #pragma unroll
    for (int i = 0; i < 4; i++)
        #pragma unroll
        for (int j = 0; j < 4; j++) o[i][j] = 0.f;
    float rsacc[4] = {0.f, 0.f, 0.f, 0.f};

    auto stage = [&](int jc, int s) {
        const int j0 = j0base + jc * CHUNK;
        const unsigned kd = sbase + s * STAGE_SZ + K_OFF;
        const unsigned vd = sbase + s * STAGE_SZ + V_OFF;
        const unsigned ad = sbase + s * STAGE_SZ + A_OFF;
        {
            int e = tid, r = e / 6, c = e - r * 6;
            cp16(kd + (r * KPAD + c * 8) * 2, g_ka + (krow0 + j0 + r) * FEAT + c * 8);
            e = tid + 256;
            if (e < 384) {
                r = e / 6; c = e - r * 6;
                cp16(kd + (r * KPAD + c * 8) * 2, g_ka + (krow0 + j0 + r) * FEAT + c * 8);
            }
        }
        {
            int r = tid >> 3, c = tid & 7;
            cp16(vd + (r * VPAD + c * 8) * 2, g_vt + (vtrow0 + r) * SEQ + j0 + c * 8);
        }
        #pragma unroll
        for (int i = 0; i < 4; i++) {
            int e = tid + i * 256, r = e >> 3, c = e & 7;
            cp16(ad + (r * APAD + c * 8) * 2, g_adjb + (size_t)(q0 + r) * SEQ + j0 + c * 8);
        }
    };

    stage(0, 0);
    asm volatile("cp.async.commit_group;");

    for (int jc = 0; jc < NCHS; jc++) {
        const int s = jc & 1;
        if (jc + 1 < NCHS) {
            stage(jc + 1, s ^ 1);
            asm volatile("cp.async.commit_group;");
            asm volatile("cp.async.wait_group 1;");
        } else {
            asm volatile("cp.async.wait_group 0;");
        }
        __syncthreads();

        const __nv_bfloat16* Ks   = (const __nv_bfloat16*)(smem_raw + s * STAGE_SZ + K_OFF);
        const __nv_bfloat16* Vts  = (const __nv_bfloat16*)(smem_raw + s * STAGE_SZ + V_OFF);
        const __nv_bfloat16* Adjs = (const __nv_bfloat16*)(smem_raw + s * STAGE_SZ + A_OFF);

        #pragma unroll
        for (int gl = 0; gl < 4; gl++) {
            uint2 ua = *(const uint2*)&Adjs[(qrow + gid) * APAD + gl * 16 + 4 * tig];
            uint2 ub = *(const uint2*)&Adjs[(qrow + gid + 8) * APAD + gl * 16 + 4 * tig];
            unsigned pa[4];
            #pragma unroll
            for (int t = 0; t < 2; t++) {
                const int kr = gl * 16 + t * 8;
                const unsigned wa = t ? ua.y : ua.x;
                const unsigned wb = t ? ub.y : ub.x;
                float c0 = bflo(wa), c1 = bfhi(wa);
                float c2 = bflo(wb), c3 = bfhi(wb);
                #pragma unroll
                for (int kk = 0; kk < 3; kk++) {
                    uint2 bb = *(const uint2*)&Ks[(kr + gid) * KPAD + 16 * kk + 4 * tig];
                    mma16816(c0, c1, c2, c3,
                             qa[kk][0], qa[kk][1], qa[kk][2], qa[kk][3], bb.x, bb.y);
                }
                pa[2 * t]     = ex2_bf16x2(packbf(c0, c1));
                pa[2 * t + 1] = ex2_bf16x2(packbf(c2, c3));
            }
            mma16816(rsacc[0], rsacc[1], rsacc[2], rsacc[3],
                     pa[0], pa[1], pa[2], pa[3], ONESBF, ONESBF);
            #pragma unroll
            for (int nf = 0; nf < 4; nf++) {
                uint2 bb = *(const uint2*)&Vts[(8 * nf + gid) * VPAD + 16 * gl + 4 * tig];
                mma16816(o[nf][0], o[nf][1], o[nf][2], o[nf][3],
                         pa[0], pa[1], pa[2], pa[3], bb.x, bb.y);
            }
        }
        __syncthreads();
    }

    // write bf16 partials (attention path tolerates this easily)
    const size_t prow = ((size_t)split * BATCH * HEADS + bh) * SEQ + q0 + qrow + gid;
    #pragma unroll
    for (int nf = 0; nf < 4; nf++) {
        *(unsigned*)&g_pob[prow * HD + 8 * nf + 2 * tig]       = packbf(o[nf][0], o[nf][1]);
        *(unsigned*)&g_pob[(prow + 8) * HD + 8 * nf + 2 * tig] = packbf(o[nf][2], o[nf][3]);
    }
    if (tig == 0) {
        g_pl[prow]     = rsacc[0];
        g_pl[prow + 8] = rsacc[2];
    }
}

// =============================================================================
// Kernel C: combine split-K partials + output projection + residual +
// LayerNorm + reg tail. Warp per row.
// =============================================================================
__global__ __launch_bounds__(256) void epi_kernel(
    const float* __restrict__ x, const float* __restrict__ Wol,
    const float* __restrict__ bol, const float* __restrict__ Woh,
    const float* __restrict__ boh, const float* __restrict__ gamma,
    const float* __restrict__ beta, const float* __restrict__ log_reg_w,
    float* __restrict__ out, int out_size)
{
    const int warp = threadIdx.x >> 5;
    const int lane = threadIdx.x & 31;
    const int row  = blockIdx.x * 8 + warp;
    const int b    = row >> 11;
    const int n    = row & (SEQ - 1);

    float ov[4];
    #pragma unroll
    for (int i = 0; i < 4; i++) {
        size_t r0 = ((size_t)(b * HEADS + i)) * SEQ + n;
        size_t r1 = ((size_t)(BATCH * HEADS) * SEQ) + r0;
        float l = g_pl[r0] + g_pl[r1];
        float p0 = __bfloat162float(g_pob[r0 * HD + lane]);
        float p1 = __bfloat162float(g_pob[r1 * HD + lane]);
        ov[i] = (p0 + p1) / l;
    }

    float t8[8];
    #pragma unroll
    for (int r = 0; r < 8; r++) t8[r] = 0.f;
    #pragma unroll
    for (int i = 0; i < 4; i++) {
        const int d = lane + 32 * i;
        const float4* wp = (const float4*)(Wol + d * RNK);
        float4 w0 = wp[0], w1 = wp[1];
        t8[0] = fmaf(ov[i], w0.x, t8[0]);
        t8[1] = fmaf(ov[i], w0.y, t8[1]);
        t8[2] = fmaf(ov[i], w0.z, t8[2]);
        t8[3] = fmaf(ov[i], w0.w, t8[3]);
        t8[4] = fmaf(ov[i], w1.x, t8[4]);
        t8[5] = fmaf(ov[i], w1.y, t8[5]);
        t8[6] = fmaf(ov[i], w1.z, t8[6]);
        t8[7] = fmaf(ov[i], w1.w, t8[7]);
    }
    #pragma unroll
    for (int r = 0; r < 8; r++) {
        #pragma unroll
        for (int off = 16; off > 0; off >>= 1)
            t8[r] += __shfl_xor_sync(0xffffffffu, t8[r], off);
        t8[r] += bol[r];
    }

    float y[4];
    #pragma unroll
    for (int i = 0; i < 4; i++) {
        const int d = lane + 32 * i;
        float o2 = boh[d];
        #pragma unroll
        for (int r = 0; r < 8; r++) o2 = fmaf(t8[r], Woh[r * HDIM + d], o2);
        y[i] = o2 + x[(size_t)row * HDIM + d];
    }

    float s = y[0] + y[1] + y[2] + y[3];
    #pragma unroll
    for (int off = 16; off > 0; off >>= 1)
        s += __shfl_xor_sync(0xffffffffu, s, off);
    const float mu = s * (1.0f / HDIM);

    float v = 0.f;
    #pragma unroll
    for (int i = 0; i < 4; i++) { y[i] -= mu; v = fmaf(y[i], y[i], v); }
    #pragma unroll
    for (int off = 16; off > 0; off >>= 1)
        v += __shfl_xor_sync(0xffffffffu, v, off);
    const float rstd = rsqrtf(v * (1.0f / HDIM) + 1e-5f);

    #pragma unroll
    for (int i = 0; i < 4; i++) {
        const int d = lane + 32 * i;
        out[(size_t)row * HDIM + d] = y[i] * rstd * gamma[d] + beta[d];
    }

    if (row == 0 && lane == 0) {
        float reg = expf(log_reg_w[0]) * (1.0f / (float)SEQ);
        for (int i = NTOT; i < out_size; i++) out[i] = reg;
    }
}

// =============================================================================
extern "C" void kernel_launch(void* const* d_in, const int* in_sizes, int n_in,
                              void* d_out, int out_size)
{
    const float* x         = (const float*)d_in[0];
    const float* Wql       = (const float*)d_in[1];
    const float* bql       = (const float*)d_in[2];
    const float* Wqh       = (const float*)d_in[3];
    const float* bqh       = (const float*)d_in[4];
    const float* u         = (const float*)d_in[5];
    const float* v         = (const float*)d_in[6];
    const float* adj_scale = (const float*)d_in[7];
    const float* Wol       = (const float*)d_in[8];
    const float* bol       = (const float*)d_in[9];
    const float* Woh       = (const float*)d_in[10];
    const float* boh       = (const float*)d_in[11];
    const float* gamma     = (const float*)d_in[12];
    const float* beta      = (const float*)d_in[13];
    const float* log_reg_w = (const float*)d_in[14];
    const float* adj_prior = (const float*)d_in[15];
    float* out = (float*)d_out;

    static bool attr_set = false;
    if (!attr_set) {
        cudaFuncSetAttribute(attn_kernel,
                             cudaFuncAttributeMaxDynamicSharedMemorySize, ATTN_SMEM);
        cudaFuncSetAttribute(qkv_fused,
                             cudaFuncAttributeMaxDynamicSharedMemorySize, QKV_SMEM);
        attr_set = true;
    }

    prep_kernel<<<1024 + 32, 256>>>(adj_prior, adj_scale, u, v);
    qkv_fused<<<(BATCH * SEQ) / QROWS, 384, QKV_SMEM>>>(x, Wql, bql, Wqh, bqh);
    attn_kernel<<<dim3((SEQ / QTILE) * KSPLIT, HEADS, BATCH), 256, ATTN_SMEM>>>();
    epi_kernel<<<(BATCH * SEQ) / 8, 256>>>(x, Wol, bol, Woh, boh, gamma, beta,
                                           log_reg_w, out, out_size);
}

// round 15
// speedup vs baseline: 1.0228x; 1.0228x over previous
#include <cuda_runtime.h>
#include <cuda_bf16.h>
#include <math.h>

#define BATCH 4
#define SEQ   2048
#define HDIM  128
#define HEADS 4
#define HD    32
#define RNK   8
#define FEAT  48            // 32 (qk) + 8 (u/v bias) + 8 zero pad
#define KPAD  48
#define VPAD  80
#define APAD  80            // 40 words == 8 mod 32 -> conflict-free LDS.64
#define QTILE 128
#define CHUNK 64
#define KSPLIT 2
#define NCHS  (SEQ / KSPLIT / CHUNK)           // 16 chunks per split
#define NTOT  (BATCH * SEQ * HDIM)
#define LOG2E 1.4426950408889634f
#define ONESBF 0x3F803F80u                     // bf16 {1.0, 1.0}

// attn smem stage layout (bytes)
#define K_OFF    0
#define K_BYTES  (CHUNK * KPAD * 2)            // 6144
#define V_OFF    K_BYTES
#define V_BYTES  (HD * VPAD * 2)               // 5120
#define A_OFF    (V_OFF + V_BYTES)             // 11264
#define A_BYTES  (QTILE * APAD * 2)            // 20480
#define STAGE_SZ (A_OFF + A_BYTES)             // 31744
#define ATTN_SMEM (2 * STAGE_SZ)               // 63488

// fused qkv smem layout (bytes)
#define QF_WQH   0                             // 24*384*4 = 36864 (reused as sq/sk)
#define QF_TSM   36864                         // 32*28*4  = 3584
#define QF_XS    40448                         // 32*132*4 = 16896
#define QF_WS    57344                         // 128*24*4 = 12288
#define QKV_SMEM 69632

// ---------------- static device scratch ------------------------------------
__device__ __align__(16) __nv_bfloat16 g_qa[BATCH * HEADS * SEQ * FEAT];
__device__ __align__(16) __nv_bfloat16 g_ka[BATCH * HEADS * SEQ * FEAT];
__device__ __align__(16) __nv_bfloat16 g_vt[BATCH * HEADS * HD * SEQ];
__device__ __align__(16) __nv_bfloat16 g_adjb[SEQ * SEQ];   // softplus*log2e scaled, key-perm16
__device__ __align__(16) __nv_bfloat16 g_pob[KSPLIT * BATCH * HEADS * SEQ * HD];  // bf16 partials
__device__ __align__(16) float g_pl[KSPLIT * BATCH * HEADS * SEQ];

// ---------------- helpers ---------------------------------------------------
__device__ __forceinline__ unsigned packbf(float lo, float hi) {
    unsigned r;
    asm("cvt.rn.bf16x2.f32 %0, %1, %2;" : "=r"(r) : "f"(hi), "f"(lo));
    return r;
}
__device__ __forceinline__ float bflo(unsigned u) { return __int_as_float(u << 16); }
__device__ __forceinline__ float bfhi(unsigned u) { return __int_as_float(u & 0xffff0000u); }
__device__ __forceinline__ unsigned ex2_bf16x2(unsigned a) {
    unsigned r;
    asm("ex2.approx.ftz.bf16x2 %0, %1;" : "=r"(r) : "r"(a));
    return r;
}

__device__ __host__ __forceinline__ int perm16(int c) {
    int g = c & ~15, c16 = c & 15;
    return g + 4 * ((c16 >> 1) & 3) + 2 * (c16 >> 3) + (c16 & 1);
}

__device__ __forceinline__ void mma16816(float& c0, float& c1, float& c2, float& c3,
                                         unsigned a0, unsigned a1, unsigned a2, unsigned a3,
                                         unsigned b0, unsigned b1) {
    asm volatile("mma.sync.aligned.m16n8k16.row.col.f32.bf16.bf16.f32 "
                 "{%0,%1,%2,%3}, {%4,%5,%6,%7}, {%8,%9}, {%0,%1,%2,%3};"
                 : "+f"(c0), "+f"(c1), "+f"(c2), "+f"(c3)
                 : "r"(a0), "r"(a1), "r"(a2), "r"(a3), "r"(b0), "r"(b1));
}

__device__ __forceinline__ void cp16(unsigned smem_dst, const void* gsrc) {
    asm volatile("cp.async.cg.shared.global [%0], [%1], 16;" :: "r"(smem_dst), "l"(gsrc));
}

// =============================================================================
// Prologue (fused): blocks [0,1024) convert adj fp32 -> bf16 (scaled,
// key-perm16); blocks [1024,1056) write u/v into Q/K aug cols.
// =============================================================================
__global__ __launch_bounds__(256) void prep_kernel(
    const float* __restrict__ adj, const float* __restrict__ adj_scale,
    const float* __restrict__ u, const float* __restrict__ v)
{
    if (blockIdx.x < 1024) {
        const float cs = log1pf(expf(adj_scale[0])) * LOG2E;
        size_t i = (size_t)blockIdx.x * 256 + threadIdx.x;   // 16-el group index
        const float4* src = (const float4*)adj + i * 4;
        float4 fa = src[0], fb = src[1], fc = src[2], fd = src[3];
        float f[16] = {fa.x, fa.y, fa.z, fa.w, fb.x, fb.y, fb.z, fb.w,
                       fc.x, fc.y, fc.z, fc.w, fd.x, fd.y, fd.z, fd.w};
        #pragma unroll
        for (int k = 0; k < 16; k++) f[k] *= cs;
        uint4 wa, wb;
        wa.x = packbf(f[0],  f[1]);  wa.y = packbf(f[8],  f[9]);
        wa.z = packbf(f[2],  f[3]);  wa.w = packbf(f[10], f[11]);
        wb.x = packbf(f[4],  f[5]);  wb.y = packbf(f[12], f[13]);
        wb.z = packbf(f[6],  f[7]);  wb.w = packbf(f[14], f[15]);
        ((uint4*)g_adjb)[i * 2 + 0] = wa;
        ((uint4*)g_adjb)[i * 2 + 1] = wb;
        return;
    }
    int idx = (blockIdx.x - 1024) * 256 + threadIdx.x;
    if (idx >= HEADS * SEQ) return;
    int h = idx >> 11, n = idx & (SEQ - 1);
    unsigned uw[4], vw[4];
    #pragma unroll
    for (int i = 0; i < 4; i++) {
        uw[i] = packbf(u[((size_t)h * SEQ + n) * RNK + 2 * i] * LOG2E,
                       u[((size_t)h * SEQ + n) * RNK + 2 * i + 1] * LOG2E);
        vw[i] = packbf(v[((size_t)h * RNK + 2 * i) * SEQ + n],
                       v[((size_t)h * RNK + 2 * i + 1) * SEQ + n]);
    }
    #pragma unroll
    for (int b = 0; b < BATCH; b++) {
        size_t base = ((size_t)(b * HEADS + h) * SEQ + n) * FEAT + 32;
        #pragma unroll
        for (int i = 0; i < 4; i++) {
            *(unsigned*)&g_qa[base + 4 * i]     = uw[i];
            *(unsigned*)&g_ka[base + 4 * i]     = vw[i];
            *(unsigned*)&g_qa[base + 4 * i + 2] = 0u;
            *(unsigned*)&g_ka[base + 4 * i + 2] = 0u;
        }
    }
}

// =============================================================================
// Kernel A (fused): QKV = (x@Wql+bql)@Wqh+bqh -> bf16 permuted Q/K + V^T.
// =============================================================================
#define QROWS 32
#define TSPAD 28
#define SQPAD 40
__global__ __launch_bounds__(384) void qkv_fused(
    const float* __restrict__ x, const float* __restrict__ Wql,
    const float* __restrict__ bql, const float* __restrict__ Wqh,
    const float* __restrict__ bqh)
{
    extern __shared__ __align__(16) char dsm[];
    float* wqh = (float*)(dsm + QF_WQH);
    float* tsm = (float*)(dsm + QF_TSM);
    float* xs  = (float*)(dsm + QF_XS);
    float* ws  = (float*)(dsm + QF_WS);

    const int tid  = threadIdx.x;
    const int row0 = blockIdx.x * QROWS;

    for (int e = tid; e < 1024; e += 384) {
        int r = e >> 5, c4 = e & 31;
        *(float4*)&xs[r * 132 + c4 * 4] =
            ((const float4*)(x + (size_t)row0 * HDIM))[e];
    }
    for (int e = tid; e < 768; e += 384)
        ((float4*)ws)[e] = ((const float4*)Wql)[e];
    for (int e = tid; e < 2304; e += 384)
        ((float4*)wqh)[e] = ((const float4*)Wqh)[e];
    __syncthreads();

    if (tid < 128) {
        const int r    = tid >> 2;
        const int cgrp = (tid & 3) * 6;
        float acc[6];
        #pragma unroll
        for (int j = 0; j < 6; j++) acc[j] = bql[cgrp + j];
        #pragma unroll 4
        for (int d = 0; d < HDIM; d++) {
            float xv = xs[r * 132 + d];
            float2 w01 = *(const float2*)&ws[d * 24 + cgrp];
            float2 w23 = *(const float2*)&ws[d * 24 + cgrp + 2];
            float2 w45 = *(const float2*)&ws[d * 24 + cgrp + 4];
            acc[0] = fmaf(xv, w01.x, acc[0]);
            acc[1] = fmaf(xv, w01.y, acc[1]);
            acc[2] = fmaf(xv, w23.x, acc[2]);
            acc[3] = fmaf(xv, w23.y, acc[3]);
            acc[4] = fmaf(xv, w45.x, acc[4]);
            acc[5] = fmaf(xv, w45.y, acc[5]);
        }
        #pragma unroll
        for (int j = 0; j < 6; j++) tsm[r * TSPAD + cgrp + j] = acc[j];
    }
    __syncthreads();

    const int c = tid;
    float wv[24];
    #pragma unroll
    for (int rk = 0; rk < 24; rk++) wv[rk] = wqh[rk * 384 + c];
    const float bias = bqh[c];
    __syncthreads();

    float acc[QROWS];
    #pragma unroll
    for (int row = 0; row < QROWS; row++) {
        float a = bias;
        #pragma unroll
        for (int k4 = 0; k4 < 6; k4++) {
            float4 t = *(const float4*)&tsm[row * TSPAD + k4 * 4];
            a = fmaf(t.x, wv[k4 * 4 + 0], a);
            a = fmaf(t.y, wv[k4 * 4 + 1], a);
            a = fmaf(t.z, wv[k4 * 4 + 2], a);
            a = fmaf(t.w, wv[k4 * 4 + 3], a);
        }
        acc[row] = a;
    }

    const int b  = row0 >> 11;
    const int n0 = row0 & (SEQ - 1);
    const int which = c >> 7;
    const int cc = c & 127;
    const int hh = cc >> 5, dd = cc & 31;
    const float qscale = 0.17677669529663687f * LOG2E;

    __nv_bfloat16* sq = (__nv_bfloat16*)(dsm + QF_WQH);
    __nv_bfloat16* sk = sq + 128 * SQPAD;

    if (which < 2) {
        const int col = perm16(dd);
        __nv_bfloat16* s = (which == 0) ? sq : sk;
        const float sc = (which == 0) ? qscale : 1.0f;
        #pragma unroll
        for (int row = 0; row < QROWS; row++)
            s[(hh * 32 + row) * SQPAD + col] = __float2bfloat16(acc[row] * sc);
    } else {
        size_t base = ((size_t)(b * HEADS + hh) * HD + dd) * SEQ + n0;
        #pragma unroll
        for (int gset = 0; gset < 2; gset++) {
            const float* a = acc + gset * 16;
            uint4 w0, w1;
            w0.x = packbf(a[0],  a[1]);  w0.y = packbf(a[8],  a[9]);
            w0.z = packbf(a[2],  a[3]);  w0.w = packbf(a[10], a[11]);
            w1.x = packbf(a[4],  a[5]);  w1.y = packbf(a[12], a[13]);
            w1.z = packbf(a[6],  a[7]);  w1.w = packbf(a[14], a[15]);
            *(uint4*)&g_vt[base + gset * 16 + 0] = w0;
            *(uint4*)&g_vt[base + gset * 16 + 8] = w1;
        }
    }
    __syncthreads();

    for (int e = tid; e < 1024; e += 384) {
        const int m   = e >> 9;
        const int idx = e & 511;
        const int orow = idx >> 2;
        const int seg  = idx & 3;
        const int ohh = orow >> 5, orr = orow & 31;
        const __nv_bfloat16* s = (m == 0) ? sq : sk;
        uint4 val = *(const uint4*)&s[orow * SQPAD + seg * 8];
        __nv_bfloat16* g = (m == 0) ? g_qa : g_ka;
        *(uint4*)&g[((size_t)(b * HEADS + ohh) * SEQ + n0 + orr) * FEAT + seg * 8] = val;
    }
}

// =============================================================================
// Kernel B: tensor-core attention, split-K (unchanged from round 14).
// =============================================================================
__global__ __launch_bounds__(256, 3) void attn_kernel()
{
    extern __shared__ __align__(16) char smem_raw[];

    const int tid  = threadIdx.x;
    const int lane = tid & 31;
    const int warp = tid >> 5;
    const int gid  = lane >> 2;
    const int tig  = lane & 3;
    const int h = blockIdx.y, b = blockIdx.z;
    const int qt    = blockIdx.x >> 1;
    const int split = blockIdx.x & 1;
    const int q0 = qt * QTILE;
    const int j0base = split * (SEQ / KSPLIT);
    const int qrow = warp * 16;

    const size_t bh     = (size_t)(b * HEADS + h);
    const size_t krow0  = bh * SEQ;
    const size_t vtrow0 = bh * HD;

    const unsigned sbase = (unsigned)__cvta_generic_to_shared(smem_raw);

    unsigned qa[3][4];
    {
        const __nv_bfloat16* q0p = g_qa + (krow0 + q0 + qrow + gid) * FEAT;
        #pragma unroll
        for (int kk = 0; kk < 3; kk++) {
            uint2 t0 = *(const uint2*)(q0p + 16 * kk + 4 * tig);
            uint2 t1 = *(const uint2*)(q0p + 8 * FEAT + 16 * kk + 4 * tig);
            qa[kk][0] = t0.x; qa[kk][1] = t1.x; qa[kk][2] = t0.y; qa[kk][3] = t1.y;
        }
    }

    float o[4][4];
    #pragma unroll
    for (int i = 0; i < 4; i++)
        #pragma unroll
        for (int j = 0; j < 4; j++) o[i][j] = 0.f;
    float rsacc[4] = {0.f, 0.f, 0.f, 0.f};

    auto stage = [&](int jc, int s) {
        const int j0 = j0base + jc * CHUNK;
        const unsigned kd = sbase + s * STAGE_SZ + K_OFF;
        const unsigned vd = sbase + s * STAGE_SZ + V_OFF;
        const unsigned ad = sbase + s * STAGE_SZ + A_OFF;
        {
            int e = tid, r = e / 6, c = e - r * 6;
            cp16(kd + (r * KPAD + c * 8) * 2, g_ka + (krow0 + j0 + r) * FEAT + c * 8);
            e = tid + 256;
            if (e < 384) {
                r = e / 6; c = e - r * 6;
                cp16(kd + (r * KPAD + c * 8) * 2, g_ka + (krow0 + j0 + r) * FEAT + c * 8);
            }
        }
        {
            int r = tid >> 3, c = tid & 7;
            cp16(vd + (r * VPAD + c * 8) * 2, g_vt + (vtrow0 + r) * SEQ + j0 + c * 8);
        }
        #pragma unroll
        for (int i = 0; i < 4; i++) {
            int e = tid + i * 256, r = e >> 3, c = e & 7;
            cp16(ad + (r * APAD + c * 8) * 2, g_adjb + (size_t)(q0 + r) * SEQ + j0 + c * 8);
        }
    };

    stage(0, 0);
    asm volatile("cp.async.commit_group;");

    for (int jc = 0; jc < NCHS; jc++) {
        const int s = jc & 1;
        if (jc + 1 < NCHS) {
            stage(jc + 1, s ^ 1);
            asm volatile("cp.async.commit_group;");
            asm volatile("cp.async.wait_group 1;");
        } else {
            asm volatile("cp.async.wait_group 0;");
        }
        __syncthreads();

        const __nv_bfloat16* Ks   = (const __nv_bfloat16*)(smem_raw + s * STAGE_SZ + K_OFF);
        const __nv_bfloat16* Vts  = (const __nv_bfloat16*)(smem_raw + s * STAGE_SZ + V_OFF);
        const __nv_bfloat16* Adjs = (const __nv_bfloat16*)(smem_raw + s * STAGE_SZ + A_OFF);

        #pragma unroll
        for (int gl = 0; gl < 4; gl++) {
            uint2 ua = *(const uint2*)&Adjs[(qrow + gid) * APAD + gl * 16 + 4 * tig];
            uint2 ub = *(const uint2*)&Adjs[(qrow + gid + 8) * APAD + gl * 16 + 4 * tig];
            unsigned pa[4];
            #pragma unroll
            for (int t = 0; t < 2; t++) {
                const int kr = gl * 16 + t * 8;
                const unsigned wa = t ? ua.y : ua.x;
                const unsigned wb = t ? ub.y : ub.x;
                float c0 = bflo(wa), c1 = bfhi(wa);
                float c2 = bflo(wb), c3 = bfhi(wb);
                #pragma unroll
                for (int kk = 0; kk < 3; kk++) {
                    uint2 bb = *(const uint2*)&Ks[(kr + gid) * KPAD + 16 * kk + 4 * tig];
                    mma16816(c0, c1, c2, c3,
                             qa[kk][0], qa[kk][1], qa[kk][2], qa[kk][3], bb.x, bb.y);
                }
                pa[2 * t]     = ex2_bf16x2(packbf(c0, c1));
                pa[2 * t + 1] = ex2_bf16x2(packbf(c2, c3));
            }
            mma16816(rsacc[0], rsacc[1], rsacc[2], rsacc[3],
                     pa[0], pa[1], pa[2], pa[3], ONESBF, ONESBF);
            #pragma unroll
            for (int nf = 0; nf < 4; nf++) {
                uint2 bb = *(const uint2*)&Vts[(8 * nf + gid) * VPAD + 16 * gl + 4 * tig];
                mma16816(o[nf][0], o[nf][1], o[nf][2], o[nf][3],
                         pa[0], pa[1], pa[2], pa[3], bb.x, bb.y);
            }
        }
        __syncthreads();
    }

    const size_t prow = ((size_t)split * BATCH * HEADS + bh) * SEQ + q0 + qrow + gid;
    #pragma unroll
    for (int nf = 0; nf < 4; nf++) {
        *(unsigned*)&g_pob[prow * HD + 8 * nf + 2 * tig]       = packbf(o[nf][0], o[nf][1]);
        *(unsigned*)&g_pob[(prow + 8) * HD + 8 * nf + 2 * tig] = packbf(o[nf][2], o[nf][3]);
    }
    if (tig == 0) {
        g_pl[prow]     = rsacc[0];
        g_pl[prow + 8] = rsacc[2];
    }
}

// =============================================================================
// Kernel C: combine split-K partials + output projection + residual +
// LayerNorm + reg tail. 512 threads = 16 rows; Wol/Woh staged in smem once
// per block; all global loads issued before the staging barrier.
// =============================================================================
#define EROWS 16
__global__ __launch_bounds__(512) void epi_kernel(
    const float* __restrict__ x, const float* __restrict__ Wol,
    const float* __restrict__ bol, const float* __restrict__ Woh,
    const float* __restrict__ boh, const float* __restrict__ gamma,
    const float* __restrict__ beta, const float* __restrict__ log_reg_w,
    float* __restrict__ out, int out_size)
{
    __shared__ float wol_s[HDIM * RNK];   // 4 KB
    __shared__ float woh_s[RNK * HDIM];   // 4 KB
    __shared__ float bol_s[RNK];

    const int tid  = threadIdx.x;
    const int warp = tid >> 5;
    const int lane = tid & 31;
    const int row  = blockIdx.x * EROWS + warp;
    const int b    = row >> 11;
    const int n    = row & (SEQ - 1);

    // ---- issue ALL global loads up front (independent of smem staging) ----
    unsigned pw0[4], pw1[4];          // bf16 partials (this lane covers d=lane
    float pl0[4], pl1[4];             // via 2B loads; keep as round-14 layout)
    float xr[4], bohr[4], gr[4], btr[4];
    #pragma unroll
    for (int i = 0; i < 4; i++) {
        size_t r0 = ((size_t)(b * HEADS + i)) * SEQ + n;
        size_t r1 = ((size_t)(BATCH * HEADS) * SEQ) + r0;
        pw0[i] = (unsigned)*(const unsigned short*)&g_pob[r0 * HD + lane];
        pw1[i] = (unsigned)*(const unsigned short*)&g_pob[r1 * HD + lane];
        pl0[i] = g_pl[r0];
        pl1[i] = g_pl[r1];
        const int d = lane + 32 * i;
        xr[i]   = x[(size_t)row * HDIM + d];
        bohr[i] = boh[d];
        gr[i]   = gamma[d];
        btr[i]  = beta[d];
    }

    // ---- stage weights in smem (once per 16 rows) ----
    #pragma unroll
    for (int e = tid; e < 256; e += 512)
        ((float4*)wol_s)[e] = ((const float4*)Wol)[e];
    #pragma unroll
    for (int e = tid; e < 256; e += 512)
        ((float4*)woh_s)[e] = ((const float4*)Woh)[e];
    if (tid < RNK) bol_s[tid] = bol[tid];
    __syncthreads();

    float ov[4];
    #pragma unroll
    for (int i = 0; i < 4; i++) {
        float l = pl0[i] + pl1[i];
        ov[i] = (__int_as_float(pw0[i] << 16) + __int_as_float(pw1[i] << 16)) / l;
    }

    float t8[8];
    #pragma unroll
    for (int r = 0; r < 8; r++) t8[r] = 0.f;
    #pragma unroll
    for (int i = 0; i < 4; i++) {
        const int d = lane + 32 * i;
        const float4* wp = (const float4*)(wol_s + d * RNK);
        float4 w0 = wp[0], w1 = wp[1];
        t8[0] = fmaf(ov[i], w0.x, t8[0]);
        t8[1] = fmaf(ov[i], w0.y, t8[1]);
        t8[2] = fmaf(ov[i], w0.z, t8[2]);
        t8[3] = fmaf(ov[i], w0.w, t8[3]);
        t8[4] = fmaf(ov[i], w1.x, t8[4]);
        t8[5] = fmaf(ov[i], w1.y, t8[5]);
        t8[6] = fmaf(ov[i], w1.z, t8[6]);
        t8[7] = fmaf(ov[i], w1.w, t8[7]);
    }
    #pragma unroll
    for (int r = 0; r < 8; r++) {
        #pragma unroll
        for (int off = 16; off > 0; off >>= 1)
            t8[r] += __shfl_xor_sync(0xffffffffu, t8[r], off);
        t8[r] += bol_s[r];
    }

    float y[4];
    #pragma unroll
    for (int i = 0; i < 4; i++) {
        const int d = lane + 32 * i;
        float o2 = bohr[i];
        #pragma unroll
        for (int r = 0; r < 8; r++) o2 = fmaf(t8[r], woh_s[r * HDIM + d], o2);
        y[i] = o2 + xr[i];
    }

    float s = y[0] + y[1] + y[2] + y[3];
    #pragma unroll
    for (int off = 16; off > 0; off >>= 1)
        s += __shfl_xor_sync(0xffffffffu, s, off);
    const float mu = s * (1.0f / HDIM);

    float v = 0.f;
    #pragma unroll
    for (int i = 0; i < 4; i++) { y[i] -= mu; v = fmaf(y[i], y[i], v); }
    #pragma unroll
    for (int off = 16; off > 0; off >>= 1)
        v += __shfl_xor_sync(0xffffffffu, v, off);
    const float rstd = rsqrtf(v * (1.0f / HDIM) + 1e-5f);

    #pragma unroll
    for (int i = 0; i < 4; i++) {
        const int d = lane + 32 * i;
        out[(size_t)row * HDIM + d] = y[i] * rstd * gr[i] + btr[i];
    }

    if (row == 0 && lane == 0) {
        float reg = expf(log_reg_w[0]) * (1.0f / (float)SEQ);
        for (int i = NTOT; i < out_size; i++) out[i] = reg;
    }
}

// =============================================================================
extern "C" void kernel_launch(void* const* d_in, const int* in_sizes, int n_in,
                              void* d_out, int out_size)
{
    const float* x         = (const float*)d_in[0];
    const float* Wql       = (const float*)d_in[1];
    const float* bql       = (const float*)d_in[2];
    const float* Wqh       = (const float*)d_in[3];
    const float* bqh       = (const float*)d_in[4];
    const float* u         = (const float*)d_in[5];
    const float* v         = (const float*)d_in[6];
    const float* adj_scale = (const float*)d_in[7];
    const float* Wol       = (const float*)d_in[8];
    const float* bol       = (const float*)d_in[9];
    const float* Woh       = (const float*)d_in[10];
    const float* boh       = (const float*)d_in[11];
    const float* gamma     = (const float*)d_in[12];
    const float* beta      = (const float*)d_in[13];
    const float* log_reg_w = (const float*)d_in[14];
    const float* adj_prior = (const float*)d_in[15];
    float* out = (float*)d_out;

    static bool attr_set = false;
    if (!attr_set) {
        cudaFuncSetAttribute(attn_kernel,
                             cudaFuncAttributeMaxDynamicSharedMemorySize, ATTN_SMEM);
        cudaFuncSetAttribute(qkv_fused,
                             cudaFuncAttributeMaxDynamicSharedMemorySize, QKV_SMEM);
        attr_set = true;
    }

    prep_kernel<<<1024 + 32, 256>>>(adj_prior, adj_scale, u, v);
    qkv_fused<<<(BATCH * SEQ) / QROWS, 384, QKV_SMEM>>>(x, Wql, bql, Wqh, bqh);
    attn_kernel<<<dim3((SEQ / QTILE) * KSPLIT, HEADS, BATCH), 256, ATTN_SMEM>>>();
    epi_kernel<<<(BATCH * SEQ) / EROWS, 512>>>(x, Wol, bol, Woh, boh, gamma, beta,
                                               log_reg_w, out, out_size);
}